// round 5
// baseline (speedup 1.0000x reference)
#include <cuda_runtime.h>

#define N_NODES 50000
#define N_EDGES 1600000
#define ND 64
#define HD 128
#define ED 32
#define MI 160
#define EB 8
#define NWARPS 8
#define THREADS (NWARPS * 32)
#define PADK2 162   // u64 per row of paired W1 (quarter-warp conflict-free LDS.128)
#define FULLMASK 0xffffffffu

typedef unsigned long long u64;

// Scratch (no cudaMalloc allowed): packed int32 edge indices + dtype flag.
__device__ int g_is64;
__device__ int g_src[N_EDGES];
__device__ int g_dst[N_EDGES];

// ---------------------------------------------------------------------------
__global__ void detect_kernel(const unsigned int* __restrict__ w) {
    if (blockIdx.x == 0 && threadIdx.x == 0) {
        int is64 = 1;
        for (int i = 0; i < 64; i++) {
            if (w[2 * i + 1] != 0u) { is64 = 0; break; }
        }
        g_is64 = is64;
    }
}

__global__ void convert_kernel(const void* __restrict__ p) {
    int i = blockIdx.x * blockDim.x + threadIdx.x;
    if (i >= N_EDGES) return;
    if (g_is64) {
        const long long* q = (const long long*)p;
        g_src[i] = (int)q[i];
        g_dst[i] = (int)q[N_EDGES + i];
    } else {
        const int* q = (const int*)p;
        g_src[i] = q[i];
        g_dst[i] = q[N_EDGES + i];
    }
}

__global__ void init_out_kernel(const float* __restrict__ h,
                                const float* __restrict__ x,
                                float* __restrict__ out) {
    int i = blockIdx.x * blockDim.x + threadIdx.x;
    const int nh = N_NODES * ND;
    const int total = nh + N_NODES * 3;
    if (i < nh) out[i] = h[i];
    else if (i < total) out[i] = x[i - nh];
}

__device__ __forceinline__ float silu(float v) {
    return __fdividef(v, 1.0f + __expf(-v));
}

__device__ __forceinline__ u64 ffma2(u64 a, u64 b, u64 c) {
    u64 d;
    asm("fma.rn.f32x2 %0, %1, %2, %3;" : "=l"(d) : "l"(a), "l"(b), "l"(c));
    return d;
}
__device__ __forceinline__ u64 pack2(float x, float y) {
    u64 r;
    asm("mov.b64 %0, {%1, %2};" : "=l"(r) : "f"(x), "f"(y));
    return r;
}
__device__ __forceinline__ float2 unpack2(u64 v) {
    float2 f;
    asm("mov.b64 {%0, %1}, %2;" : "=f"(f.x), "=f"(f.y) : "l"(v));
    return f;
}

// ---------------------------------------------------------------------------
// Persistent grid, 1 CTA/SM, 8 warps, 8 edges/warp-task, f32x2 math.
// Broadcasts use duplicated-pair smem staging: one broadcast LDS.128 yields
// {v_k, v_k, v_{k+1}, v_{k+1}} = two FFMA2 b-operands (replaces 4 shfl+4 mov).
// ---------------------------------------------------------------------------
__global__ void __launch_bounds__(THREADS, 1)
edge_kernel(const float* __restrict__ h, const float* __restrict__ x,
            const float* __restrict__ edge_dist,
            const float* __restrict__ node_w1, const float* __restrict__ node_b1,
            const float* __restrict__ node_w2, const float* __restrict__ node_b2,
            const float* __restrict__ coord_w1, const float* __restrict__ coord_b1,
            const float* __restrict__ coord_w2,
            const float* __restrict__ edge_w1, const float* __restrict__ edge_b1,
            const float* __restrict__ edge_w2, const float* __restrict__ edge_b2,
            float* __restrict__ out) {
    extern __shared__ float smem[];
    u64* s_nw1p = (u64*)smem;                       // 64 * PADK2 u64
    u64* s_cw1p = s_nw1p + 64 * PADK2;              // 64 * PADK2 u64
    u64* s_stage = s_cw1p + 64 * PADK2;             // NWARPS*EB*32 u64 (16KB)
    float* s_nw2p = (float*)(s_stage + NWARPS * EB * 32);  // 64*128 floats
    float* s_ew2 = s_nw2p + 64 * 128;               // 32*32
    float* s_cw2 = s_ew2 + ED * ED;                 // 128
    float* s_nb1 = s_cw2 + HD;                      // 128
    float* s_cb1 = s_nb1 + HD;                      // 128
    float* s_nb2 = s_cb1 + HD;                      // 64
    float* s_ew1 = s_nb2 + ND;                      // 32
    float* s_eb1 = s_ew1 + ED;                      // 32
    float* s_eb2 = s_eb1 + ED;                      // 32

    const int tid = threadIdx.x;
    // W1 paired: ((p*32+l)*PADK2 + k) = {W[k][l+64p], W[k][l+32+64p]}
    {
        float* nf = (float*)s_nw1p;
        float* cf = (float*)s_cw1p;
        for (int idx = tid; idx < MI * HD; idx += THREADS) {
            int k = idx / HD, j = idx % HD;
            int p = j >> 6;
            int jr = j & 63;
            int l = jr & 31;
            int hi = jr >> 5;
            int off = ((p * 32 + l) * PADK2 + k) * 2 + hi;
            nf[off] = node_w1[idx];
            cf[off] = coord_w1[idx];
        }
    }
    // W2 h-pair interleaved: row hp holds float4 per lane:
    // {W[2hp][2l], W[2hp][2l+1], W[2hp+1][2l], W[2hp+1][2l+1]}
    for (int idx = tid; idx < HD * ND; idx += THREADS) {
        int hh = idx / ND, j = idx % ND;
        int hp = hh >> 1, hin = hh & 1;
        int l = j >> 1, jc = j & 1;
        s_nw2p[hp * 128 + l * 4 + hin * 2 + jc] = node_w2[idx];
    }
    for (int i = tid; i < ED * ED; i += THREADS) s_ew2[i] = edge_w2[i];
    if (tid < HD) {
        s_cw2[tid] = coord_w2[tid];
        s_nb1[tid] = node_b1[tid];
        s_cb1[tid] = coord_b1[tid];
    }
    if (tid < ND) s_nb2[tid] = node_b2[tid];
    if (tid < ED) {
        s_ew1[tid] = edge_w1[tid];
        s_eb1[tid] = edge_b1[tid];
        s_eb2[tid] = edge_b2[tid];
    }
    __syncthreads();

    const int lane = tid & 31;
    const int warp = tid >> 5;
    const int gwarp = blockIdx.x * NWARPS + warp;
    const int nwarps_total = gridDim.x * NWARPS;
    const int ntasks = N_EDGES / EB;

    float* out_h = out;
    float* out_x = out + (size_t)N_NODES * ND;

    const u64* w1n0 = s_nw1p + (size_t)lane * PADK2;
    const u64* w1n1 = s_nw1p + (size_t)(32 + lane) * PADK2;
    const u64* w1c0 = s_cw1p + (size_t)lane * PADK2;
    const u64* w1c1 = s_cw1p + (size_t)(32 + lane) * PADK2;
    u64* stg = s_stage + (size_t)warp * EB * 32;  // [EB][32] u64, warp-private

    for (int task = gwarp; task < ntasks; task += nwarps_total) {
        const int ebase = task * EB;

        int src[EB], dst[EB];
        float dist[EB];
#pragma unroll
        for (int i = 0; i < EB; i++) {
            int e = ebase + i;
            src[i] = g_src[e];
            dst[i] = g_dst[e];
            dist[i] = edge_dist[e];
        }

        // ---- gather h early
        float mi[EB][5];
#pragma unroll
        for (int i = 0; i < EB; i++) {
            const float* hs = h + (size_t)src[i] * ND;
            const float* hd = h + (size_t)dst[i] * ND;
            mi[i][0] = hs[lane];
            mi[i][1] = hs[32 + lane];
            mi[i][2] = hd[lane];
            mi[i][3] = hd[32 + lane];
        }

        // ---- edge MLP (small; shfl broadcast)
#pragma unroll
        for (int i = 0; i < EB; i++) {
            float t = silu(fmaf(dist[i], s_ew1[lane], s_eb1[lane]));
            float acc = s_eb2[lane];
#pragma unroll 8
            for (int k = 0; k < ED; k++) {
                float tv = __shfl_sync(FULLMASK, t, k);
                acc = fmaf(tv, s_ew2[k * ED + lane], acc);
            }
            mi[i][4] = acc;
        }

        // ---- hidden layers: anp[i][p] = {act[lane+64p], act[lane+32+64p]}
        u64 anp[EB][2], acp[EB][2];
#pragma unroll
        for (int i = 0; i < EB; i++) {
#pragma unroll
            for (int p = 0; p < 2; p++) {
                anp[i][p] = pack2(s_nb1[lane + 64 * p], s_nb1[lane + 64 * p + 32]);
                acp[i][p] = pack2(s_cb1[lane + 64 * p], s_cb1[lane + 64 * p + 32]);
            }
        }

#pragma unroll
        for (int seg = 0; seg < 5; seg++) {
            __syncwarp();
#pragma unroll
            for (int i = 0; i < EB; i++)
                stg[i * 32 + lane] = pack2(mi[i][seg], mi[i][seg]);
            __syncwarp();
#pragma unroll 4
            for (int kk = 0; kk < 32; kk += 2) {
                const int k = seg * 32 + kk;
                ulonglong2 wn0 = *(const ulonglong2*)(w1n0 + k);
                ulonglong2 wn1 = *(const ulonglong2*)(w1n1 + k);
                ulonglong2 wc0 = *(const ulonglong2*)(w1c0 + k);
                ulonglong2 wc1 = *(const ulonglong2*)(w1c1 + k);
#pragma unroll
                for (int i = 0; i < EB; i++) {
                    ulonglong2 b = *(const ulonglong2*)&stg[i * 32 + kk];
                    anp[i][0] = ffma2(b.x, wn0.x, anp[i][0]);
                    anp[i][1] = ffma2(b.x, wn1.x, anp[i][1]);
                    acp[i][0] = ffma2(b.x, wc0.x, acp[i][0]);
                    acp[i][1] = ffma2(b.x, wc1.x, acp[i][1]);
                    anp[i][0] = ffma2(b.y, wn0.y, anp[i][0]);
                    anp[i][1] = ffma2(b.y, wn1.y, anp[i][1]);
                    acp[i][0] = ffma2(b.y, wc0.y, acp[i][0]);
                    acp[i][1] = ffma2(b.y, wc1.y, acp[i][1]);
                }
            }
        }

        // ---- unpack + silu; sn[i][r] = act at hidden unit h = lane + 32r
        float sn[EB][4], sc[EB][4];
#pragma unroll
        for (int i = 0; i < EB; i++) {
            float2 a0 = unpack2(anp[i][0]), a1 = unpack2(anp[i][1]);
            float2 c0 = unpack2(acp[i][0]), c1 = unpack2(acp[i][1]);
            sn[i][0] = silu(a0.x); sn[i][1] = silu(a0.y);
            sn[i][2] = silu(a1.x); sn[i][3] = silu(a1.y);
            sc[i][0] = silu(c0.x); sc[i][1] = silu(c0.y);
            sc[i][2] = silu(c1.x); sc[i][3] = silu(c1.y);
        }

        // ---- node out: o2[i] covers j = (2*lane, 2*lane+1)
        u64 o2[EB];
        {
            u64 binit = *(const u64*)&s_nb2[2 * lane];
#pragma unroll
            for (int i = 0; i < EB; i++) o2[i] = binit;
        }
#pragma unroll
        for (int r = 0; r < 4; r++) {
            __syncwarp();
#pragma unroll
            for (int i = 0; i < EB; i++)
                stg[i * 32 + lane] = pack2(sn[i][r], sn[i][r]);
            __syncwarp();
#pragma unroll 4
            for (int hb = 0; hb < 32; hb += 2) {
                const int hp = (r * 32 + hb) >> 1;
                ulonglong2 w = *(const ulonglong2*)&s_nw2p[hp * 128 + lane * 4];
#pragma unroll
                for (int i = 0; i < EB; i++) {
                    ulonglong2 b = *(const ulonglong2*)&stg[i * 32 + hb];
                    o2[i] = ffma2(b.x, w.x, o2[i]);
                    o2[i] = ffma2(b.y, w.y, o2[i]);
                }
            }
        }

        // ---- coord scalar via warp reduction
        float cw[EB];
#pragma unroll
        for (int i = 0; i < EB; i++) {
            float p = 0.0f;
#pragma unroll
            for (int r = 0; r < 4; r++)
                p = fmaf(sc[i][r], s_cw2[lane + 32 * r], p);
#pragma unroll
            for (int off = 16; off >= 1; off >>= 1)
                p += __shfl_xor_sync(FULLMASK, p, off);
            cw[i] = p;
        }

        // ---- scatter h_agg with float2 vector atomics
#pragma unroll
        for (int i = 0; i < EB; i++) {
            float2 ov = unpack2(o2[i]);
            float2* dsth = (float2*)(out_h + (size_t)dst[i] * ND) + lane;
            atomicAdd(dsth, ov);
        }

        // ---- scatter x_agg: lanes 0..EB-1, one edge each
        if (lane < EB) {
            int si = src[0], di = dst[0];
            float cwi = cw[0];
#pragma unroll
            for (int q = 1; q < EB; q++) {
                if (lane == q) { si = src[q]; di = dst[q]; cwi = cw[q]; }
            }
            const float* xs = x + (size_t)si * 3;
            const float* xd = x + (size_t)di * 3;
            float dx = xs[0] - xd[0];
            float dy = xs[1] - xd[1];
            float dz = xs[2] - xd[2];
            float len = fmaxf(sqrtf(dx * dx + dy * dy + dz * dz), 1e-8f);
            float s = __fdividef(cwi, len);
            float* dstx = out_x + (size_t)di * 3;
            atomicAdd(dstx + 0, s * dx);
            atomicAdd(dstx + 1, s * dy);
            atomicAdd(dstx + 2, s * dz);
        }
    }
}

// ---------------------------------------------------------------------------
extern "C" void kernel_launch(void* const* d_in, const int* in_sizes, int n_in,
                              void* d_out, int out_size) {
    const float* h        = (const float*)d_in[0];
    const float* x        = (const float*)d_in[1];
    const void*  eidx     = d_in[2];
    const float* edist    = (const float*)d_in[3];
    const float* node_w1  = (const float*)d_in[4];
    const float* node_b1  = (const float*)d_in[5];
    const float* node_w2  = (const float*)d_in[6];
    const float* node_b2  = (const float*)d_in[7];
    const float* coord_w1 = (const float*)d_in[8];
    const float* coord_b1 = (const float*)d_in[9];
    const float* coord_w2 = (const float*)d_in[10];
    const float* edge_w1  = (const float*)d_in[11];
    const float* edge_b1  = (const float*)d_in[12];
    const float* edge_w2  = (const float*)d_in[13];
    const float* edge_b2  = (const float*)d_in[14];
    float* out = (float*)d_out;

    (void)in_sizes; (void)n_in; (void)out_size;

    detect_kernel<<<1, 32>>>((const unsigned int*)eidx);
    convert_kernel<<<(N_EDGES + 255) / 256, 256>>>(eidx);

    const int total_out = N_NODES * ND + N_NODES * 3;
    init_out_kernel<<<(total_out + 255) / 256, 256>>>(h, x, out);

    const int smem_bytes =
        64 * PADK2 * 8 * 2 +            // paired nw1 + cw1 (u64)
        NWARPS * EB * 32 * 8 +          // staging
        64 * 128 * 4 +                  // paired nw2
        (ED * ED + HD * 3 + ND + ED * 3) * (int)sizeof(float);
    cudaFuncSetAttribute(edge_kernel,
                         cudaFuncAttributeMaxDynamicSharedMemorySize, smem_bytes);

    int nsm = 148;
    cudaDeviceGetAttribute(&nsm, cudaDevAttrMultiProcessorCount, 0);

    edge_kernel<<<nsm, THREADS, smem_bytes>>>(
        h, x, edist,
        node_w1, node_b1, node_w2, node_b2,
        coord_w1, coord_b1, coord_w2,
        edge_w1, edge_b1, edge_w2, edge_b2,
        out);
}

// round 7
// speedup vs baseline: 2.1717x; 2.1717x over previous
#include <cuda_runtime.h>
#include <cstdint>

#define N_NODES 50000
#define N_EDGES 1600000
#define ND 64
#define HD 128
#define ED 32
#define MI 160
#define TILE_E 32
#define NTILES (N_EDGES / TILE_E)
#define THREADS 256
#define FULLMASK 0xffffffffu

#define KT1 20
#define NT1 32
#define KT2 16
#define NT2 8
#define W1F_WORDS (KT1 * NT1 * 64)
#define W2F_WORDS (KT2 * NT2 * 64)
#define MI_STRIDE 164
#define HID_STRIDE 132

#define OFF_W1F   0
#define OFF_W2F   40960
#define OFF_MI    49152
#define OFF_EW2   54400
#define OFF_B1    55424
#define OFF_B2    55680
#define OFF_CW2   55744
#define OFF_EW1   55872
#define OFF_EB1   55904
#define OFF_EB2   55936
#define OFF_CPART 55968
#define OFF_SRC   56096
#define OFF_DST   56128
#define OFF_DIST  56160
#define SMEM_WORDS 56192

typedef unsigned int u32;

__device__ int g_is64;
__device__ int g_src[N_EDGES];
__device__ int g_dst[N_EDGES];
__device__ u32 g_w1f[W1F_WORDS];
__device__ u32 g_w2f[W2F_WORDS];

__global__ void detect_kernel(const unsigned int* __restrict__ w) {
    if (blockIdx.x == 0 && threadIdx.x == 0) {
        int is64 = 1;
        for (int i = 0; i < 64; i++)
            if (w[2 * i + 1] != 0u) { is64 = 0; break; }
        g_is64 = is64;
    }
}

__global__ void convert_kernel(const void* __restrict__ p) {
    int i = blockIdx.x * blockDim.x + threadIdx.x;
    if (i >= N_EDGES) return;
    if (g_is64) {
        const long long* q = (const long long*)p;
        g_src[i] = (int)q[i];
        g_dst[i] = (int)q[N_EDGES + i];
    } else {
        const int* q = (const int*)p;
        g_src[i] = q[i];
        g_dst[i] = q[N_EDGES + i];
    }
}

__global__ void init_out_kernel(const float* __restrict__ h,
                                const float* __restrict__ x,
                                float* __restrict__ out) {
    int i = blockIdx.x * blockDim.x + threadIdx.x;
    const int nh = N_NODES * ND;
    const int total = nh + N_NODES * 3;
    if (i < nh) out[i] = h[i];
    else if (i < total) out[i] = x[i - nh];
}

__device__ __forceinline__ u32 tf32b(float f) {
    u32 u;
    asm("cvt.rna.tf32.f32 %0, %1;" : "=r"(u) : "f"(f));
    return u;
}
__device__ __forceinline__ float silu(float v) {
    return __fdividef(v, 1.0f + __expf(-v));
}
__device__ __forceinline__ void mma_tf32(
    float& d0, float& d1, float& d2, float& d3,
    u32 a0, u32 a1, u32 a2, u32 a3, u32 b0, u32 b1) {
    asm volatile(
        "mma.sync.aligned.m16n8k8.row.col.f32.tf32.tf32.f32 "
        "{%0,%1,%2,%3}, {%4,%5,%6,%7}, {%8,%9}, {%0,%1,%2,%3};"
        : "+f"(d0), "+f"(d1), "+f"(d2), "+f"(d3)
        : "r"(a0), "r"(a1), "r"(a2), "r"(a3), "r"(b0), "r"(b1));
}

__global__ void build_frags(const float* __restrict__ nw1,
                            const float* __restrict__ cw1,
                            const float* __restrict__ nw2) {
    int i = blockIdx.x * blockDim.x + threadIdx.x;
    if (i < W1F_WORDS) {
        int word = i & 1, L = (i >> 1) & 31, nt = (i >> 6) & 31, kt = i >> 11;
        int n = nt * 8 + (L >> 2);
        int k = kt * 8 + (L & 3) + 4 * word;
        float v = (n < HD) ? nw1[k * HD + n] : cw1[k * HD + (n - HD)];
        g_w1f[i] = tf32b(v);
    }
    if (i < W2F_WORDS) {
        int word = i & 1, L = (i >> 1) & 31, nt = (i >> 6) & 7, kt = i >> 9;
        int n = nt * 8 + (L >> 2);
        int k = kt * 8 + (L & 3) + 4 * word;
        g_w2f[i] = tf32b(nw2[k * ND + n]);
    }
}

__global__ void __launch_bounds__(THREADS, 1)
egnn_mma_kernel(const float* __restrict__ h, const float* __restrict__ x,
                const float* __restrict__ edge_dist,
                const float* __restrict__ node_b1, const float* __restrict__ node_b2,
                const float* __restrict__ coord_b1, const float* __restrict__ coord_w2,
                const float* __restrict__ edge_w1, const float* __restrict__ edge_b1,
                const float* __restrict__ edge_w2, const float* __restrict__ edge_b2,
                float* __restrict__ out) {
    extern __shared__ u32 sm[];
    u32* s_w1f = sm + OFF_W1F;
    u32* s_w2f = sm + OFF_W2F;
    u32* s_mi  = sm + OFF_MI;
    float* s_ew2f = (float*)(sm + OFF_EW2);
    float* s_b1f  = (float*)(sm + OFF_B1);
    float* s_b2f  = (float*)(sm + OFF_B2);
    float* s_cw2f = (float*)(sm + OFF_CW2);
    float* s_ew1f = (float*)(sm + OFF_EW1);
    float* s_eb1f = (float*)(sm + OFF_EB1);
    float* s_eb2f = (float*)(sm + OFF_EB2);
    float* s_cpart = (float*)(sm + OFF_CPART);
    int* s_srci = (int*)(sm + OFF_SRC);
    int* s_dsti = (int*)(sm + OFF_DST);
    float* s_distf = (float*)(sm + OFF_DIST);

    const int tid = threadIdx.x;
    const int lane = tid & 31;
    const int warp = tid >> 5;

    {
        const uint4* src1 = (const uint4*)g_w1f;
        uint4* dst1 = (uint4*)s_w1f;
        for (int i = tid; i < W1F_WORDS / 4; i += THREADS) dst1[i] = src1[i];
        const uint4* src2 = (const uint4*)g_w2f;
        uint4* dst2 = (uint4*)s_w2f;
        for (int i = tid; i < W2F_WORDS / 4; i += THREADS) dst2[i] = src2[i];
    }
    for (int i = tid; i < ED * ED; i += THREADS) s_ew2f[i] = edge_w2[i];
    s_b1f[tid] = (tid < HD) ? node_b1[tid] : coord_b1[tid - HD];
    if (tid < ND) s_b2f[tid] = node_b2[tid];
    if (tid < HD) s_cw2f[tid] = coord_w2[tid];
    if (tid < ED) {
        s_ew1f[tid] = edge_w1[tid];
        s_eb1f[tid] = edge_b1[tid];
        s_eb2f[tid] = edge_b2[tid];
    }
    __syncthreads();

    float* out_h = out;
    float* out_x = out + (size_t)N_NODES * ND;

    const int r = lane >> 2;
    const int c = lane & 3;

    for (int tile = blockIdx.x; tile < NTILES; tile += gridDim.x) {
        const int e0 = tile * TILE_E;

        __syncthreads();
        if (warp == 0) {
            s_srci[lane] = g_src[e0 + lane];
            s_dsti[lane] = g_dst[e0 + lane];
            s_distf[lane] = edge_dist[e0 + lane];
        }
        __syncthreads();

        // gather h rows (tf32) ; warp4 x prefetch ; edge MLP
        {
            const int e = tid >> 3, p = tid & 7;
            const float4* hs = (const float4*)(h + (size_t)s_srci[e] * ND);
            const float4* hd = (const float4*)(h + (size_t)s_dsti[e] * ND);
            float4 v0 = hs[p], v1 = hs[p + 8], v2 = hd[p], v3 = hd[p + 8];
            uint4* mrow = (uint4*)(s_mi + e * MI_STRIDE);
            mrow[p]      = make_uint4(tf32b(v0.x), tf32b(v0.y), tf32b(v0.z), tf32b(v0.w));
            mrow[p + 8]  = make_uint4(tf32b(v1.x), tf32b(v1.y), tf32b(v1.z), tf32b(v1.w));
            mrow[p + 16] = make_uint4(tf32b(v2.x), tf32b(v2.y), tf32b(v2.z), tf32b(v2.w));
            mrow[p + 24] = make_uint4(tf32b(v3.x), tf32b(v3.y), tf32b(v3.z), tf32b(v3.w));
        }
        float xs0 = 0, xs1 = 0, xs2 = 0, xd0 = 0, xd1 = 0, xd2 = 0;
        if (warp == 4) {
            const float* xs = x + (size_t)s_srci[lane] * 3;
            const float* xd = x + (size_t)s_dsti[lane] * 3;
            xs0 = xs[0]; xs1 = xs[1]; xs2 = xs[2];
            xd0 = xd[0]; xd1 = xd[1]; xd2 = xd[2];
        }
#pragma unroll
        for (int q = 0; q < 4; q++) {
            const int e = warp * 4 + q;
            float t = silu(fmaf(s_distf[e], s_ew1f[lane], s_eb1f[lane]));
            float acc = s_eb2f[lane];
#pragma unroll 8
            for (int k = 0; k < ED; k++) {
                float tv = __shfl_sync(FULLMASK, t, k);
                acc = fmaf(tv, s_ew2f[k * ED + lane], acc);
            }
            s_mi[e * MI_STRIDE + 2 * ND + lane] = tf32b(acc);
        }
        __syncthreads();

        // MMA1: [32,160] x [160,256]; warp w -> cols 32w..32w+31
        float acc[2][4][4];
#pragma unroll
        for (int mt = 0; mt < 2; mt++)
#pragma unroll
            for (int nt = 0; nt < 4; nt++)
#pragma unroll
                for (int q = 0; q < 4; q++) acc[mt][nt][q] = 0.0f;

#pragma unroll 2
        for (int kt = 0; kt < KT1; kt++) {
            u32 a[2][4];
#pragma unroll
            for (int mt = 0; mt < 2; mt++) {
                const u32* m0 = s_mi + (mt * 16 + r) * MI_STRIDE + kt * 8;
                const u32* m8 = m0 + 8 * MI_STRIDE;
                a[mt][0] = m0[c];
                a[mt][1] = m8[c];
                a[mt][2] = m0[c + 4];
                a[mt][3] = m8[c + 4];
            }
#pragma unroll
            for (int nt = 0; nt < 4; nt++) {
                const u32* bp = s_w1f + ((kt * NT1 + (warp * 4 + nt)) * 32 + lane) * 2;
                u32 b0 = bp[0], b1 = bp[1];
#pragma unroll
                for (int mt = 0; mt < 2; mt++)
                    mma_tf32(acc[mt][nt][0], acc[mt][nt][1], acc[mt][nt][2], acc[mt][nt][3],
                             a[mt][0], a[mt][1], a[mt][2], a[mt][3], b0, b1);
            }
        }

        // coord warps: silu + weighted reduce -> cpart
        if (warp >= 4) {
            const int cw0 = (warp - 4) * 32;
#pragma unroll
            for (int mt = 0; mt < 2; mt++) {
                float pr = 0.0f, pr8 = 0.0f;
#pragma unroll
                for (int nt = 0; nt < 4; nt++) {
                    const int cc = cw0 + nt * 8 + 2 * c;
                    float b1a = s_b1f[HD + cc], b1b = s_b1f[HD + cc + 1];
                    float w2a = s_cw2f[cc], w2b = s_cw2f[cc + 1];
                    pr  = fmaf(silu(acc[mt][nt][0] + b1a), w2a, pr);
                    pr  = fmaf(silu(acc[mt][nt][1] + b1b), w2b, pr);
                    pr8 = fmaf(silu(acc[mt][nt][2] + b1a), w2a, pr8);
                    pr8 = fmaf(silu(acc[mt][nt][3] + b1b), w2b, pr8);
                }
                pr  += __shfl_xor_sync(FULLMASK, pr, 1);
                pr  += __shfl_xor_sync(FULLMASK, pr, 2);
                pr8 += __shfl_xor_sync(FULLMASK, pr8, 1);
                pr8 += __shfl_xor_sync(FULLMASK, pr8, 2);
                if (c == 0) {
                    s_cpart[(warp - 4) * 32 + mt * 16 + r] = pr;
                    s_cpart[(warp - 4) * 32 + mt * 16 + r + 8] = pr8;
                }
            }
        }
        __syncthreads();

        // node warps: silu'd hidden -> smem (tf32); warp4: coord scatter
        if (warp < 4) {
#pragma unroll
            for (int mt = 0; mt < 2; mt++)
#pragma unroll
                for (int nt = 0; nt < 4; nt++) {
                    const int col = warp * 32 + nt * 8 + 2 * c;
                    float b1a = s_b1f[col], b1b = s_b1f[col + 1];
                    u32 v0 = tf32b(silu(acc[mt][nt][0] + b1a));
                    u32 v1 = tf32b(silu(acc[mt][nt][1] + b1b));
                    u32 v2 = tf32b(silu(acc[mt][nt][2] + b1a));
                    u32 v3 = tf32b(silu(acc[mt][nt][3] + b1b));
                    u32* row0 = s_mi + (mt * 16 + r) * HID_STRIDE + col;
                    u32* row8 = row0 + 8 * HID_STRIDE;
                    *(uint2*)row0 = make_uint2(v0, v1);
                    *(uint2*)row8 = make_uint2(v2, v3);
                }
        } else if (warp == 4) {
            float cwv = s_cpart[lane] + s_cpart[32 + lane] +
                        s_cpart[64 + lane] + s_cpart[96 + lane];
            float dx = xs0 - xd0, dy = xs1 - xd1, dz = xs2 - xd2;
            float len = fmaxf(sqrtf(dx * dx + dy * dy + dz * dz), 1e-8f);
            float s = __fdividef(cwv, len);
            float* dstx = out_x + (size_t)s_dsti[lane] * 3;
            atomicAdd(dstx + 0, s * dx);
            atomicAdd(dstx + 1, s * dy);
            atomicAdd(dstx + 2, s * dz);
        }
        __syncthreads();

        // MMA2: [32,128] x [128,64]
        {
            const int mt2 = warp >> 2;
            const int nc = warp & 3;
            float a2[2][4];
#pragma unroll
            for (int nt = 0; nt < 2; nt++)
#pragma unroll
                for (int q = 0; q < 4; q++) a2[nt][q] = 0.0f;

#pragma unroll 2
            for (int kt = 0; kt < KT2; kt++) {
                const u32* m0 = s_mi + (mt2 * 16 + r) * HID_STRIDE + kt * 8;
                const u32* m8 = m0 + 8 * HID_STRIDE;
                u32 a0 = m0[c], a1 = m8[c], av2 = m0[c + 4], a3 = m8[c + 4];
#pragma unroll
                for (int nt = 0; nt < 2; nt++) {
                    const u32* bp = s_w2f + ((kt * NT2 + (nc * 2 + nt)) * 32 + lane) * 2;
                    mma_tf32(a2[nt][0], a2[nt][1], a2[nt][2], a2[nt][3],
                             a0, a1, av2, a3, bp[0], bp[1]);
                }
            }
#pragma unroll
            for (int nt = 0; nt < 2; nt++) {
                const int col = nc * 16 + nt * 8 + 2 * c;
                float b2a = s_b2f[col], b2b = s_b2f[col + 1];
                int eA = mt2 * 16 + r;
                float* baseA = out_h + (size_t)s_dsti[eA] * ND + col;
                atomicAdd((float2*)baseA, make_float2(a2[nt][0] + b2a, a2[nt][1] + b2b));
                float* baseB = out_h + (size_t)s_dsti[eA + 8] * ND + col;
                atomicAdd((float2*)baseB, make_float2(a2[nt][2] + b2a, a2[nt][3] + b2b));
            }
        }
    }
}

extern "C" void kernel_launch(void* const* d_in, const int* in_sizes, int n_in,
                              void* d_out, int out_size) {
    const float* h        = (const float*)d_in[0];
    const float* x        = (const float*)d_in[1];
    const void*  eidx     = d_in[2];
    const float* edist    = (const float*)d_in[3];
    const float* node_w1  = (const float*)d_in[4];
    const float* node_b1  = (const float*)d_in[5];
    const float* node_w2  = (const float*)d_in[6];
    const float* node_b2  = (const float*)d_in[7];
    const float* coord_w1 = (const float*)d_in[8];
    const float* coord_b1 = (const float*)d_in[9];
    const float* coord_w2 = (const float*)d_in[10];
    const float* edge_w1  = (const float*)d_in[11];
    const float* edge_b1  = (const float*)d_in[12];
    const float* edge_w2  = (const float*)d_in[13];
    const float* edge_b2  = (const float*)d_in[14];
    float* out = (float*)d_out;

    (void)in_sizes; (void)n_in; (void)out_size;

    detect_kernel<<<1, 32>>>((const unsigned int*)eidx);
    convert_kernel<<<(N_EDGES + 255) / 256, 256>>>(eidx);
    build_frags<<<(W1F_WORDS + 255) / 256, 256>>>(node_w1, coord_w1, node_w2);

    const int total_out = N_NODES * ND + N_NODES * 3;
    init_out_kernel<<<(total_out + 255) / 256, 256>>>(h, x, out);

    const int smem_bytes = SMEM_WORDS * 4;
    cudaFuncSetAttribute(egnn_mma_kernel,
                         cudaFuncAttributeMaxDynamicSharedMemorySize, smem_bytes);

    int nsm = 148;
    cudaDeviceGetAttribute(&nsm, cudaDevAttrMultiProcessorCount, 0);

    egnn_mma_kernel<<<nsm, THREADS, smem_bytes>>>(
        h, x, edist, node_b1, node_b2, coord_b1, coord_w2,
        edge_w1, edge_b1, edge_w2, edge_b2, out);
}